// round 4
// baseline (speedup 1.0000x reference)
#include <cuda_runtime.h>
#include <cuda_bf16.h>
#include <stdint.h>

#define CIN   16
#define COUT  32
#define KK    27
#define HTILE 128           // h per block
#define TPB   256
#define MAX_H 300064
#define MAX_B 4096

__device__ float g_xt[(size_t)MAX_H * CIN];  // transposed x: [h][c]; row H = zeros
__device__ float g_psum[MAX_B * COUT];
__device__ float g_psq [MAX_B * COUT];
__device__ float g_scale[COUT];
__device__ float g_shift[COUT];
__device__ int   g_is64;

// packed fp32x2 FMA: d.lo += a.lo*b.lo ; d.hi += a.hi*b.hi  (FFMA2 on sm_103a)
__device__ __forceinline__ void fma2(unsigned long long& d,
                                     unsigned long long a,
                                     unsigned long long b) {
    asm("fma.rn.f32x2 %0, %1, %2, %0;" : "+l"(d) : "l"(a), "l"(b));
}

// ---------------------------------------------------------------------------
__global__ void detect_kernel(const long long* __restrict__ neigh,
                              int H, long long n_elems) {
    __shared__ int bad;
    if (threadIdx.x == 0) bad = 0;
    __syncthreads();
    long long n64 = n_elems / 2;
    long long lim = n64 < 4096 ? n64 : 4096;
    for (long long i = threadIdx.x; i < lim; i += blockDim.x) {
        long long v = neigh[i];
        if (v < -1 || v >= (long long)H) bad = 1;
    }
    __syncthreads();
    if (threadIdx.x == 0) g_is64 = (bad == 0);
}

// ---------------------------------------------------------------------------
__global__ void transpose_kernel(const float* __restrict__ x, int H) {
    int h = blockIdx.x * blockDim.x + threadIdx.x;
    float4* dst = reinterpret_cast<float4*>(&g_xt[(size_t)h * CIN]);
    if (h < H) {
        float v[CIN];
#pragma unroll
        for (int c = 0; c < CIN; c++) v[c] = x[(size_t)c * H + h];
#pragma unroll
        for (int j = 0; j < CIN / 4; j++)
            dst[j] = make_float4(v[4 * j], v[4 * j + 1], v[4 * j + 2], v[4 * j + 3]);
    } else if (h < H + 32 && h < MAX_H) {
        float4 z = make_float4(0.f, 0.f, 0.f, 0.f);
#pragma unroll
        for (int j = 0; j < CIN / 4; j++) dst[j] = z;
    }
}

// ---------------------------------------------------------------------------
// Gather-conv, o-split layout:
//   warps 0-3 : o in [0,16)  for h-tile of 128
//   warps 4-7 : o in [16,32) for the SAME h-tile (x gathers hit L1)
// 16 f32x2 accumulators/thread; x row double-buffered across k.
// ---------------------------------------------------------------------------
__global__ __launch_bounds__(TPB, 2)
void conv_kernel(const float* __restrict__ w,
                 const void* __restrict__ neigh_raw,
                 float* __restrict__ out, int H) {
    extern __shared__ float ws[];                 // [k][o][i], 55.3 KB
    __shared__ float s_sum[TPB / 32][16];
    __shared__ float s_sq [TPB / 32][16];

    for (int idx = threadIdx.x; idx < KK * COUT * CIN; idx += TPB) {
        int k = idx / (COUT * CIN);
        int r = idx - k * (COUT * CIN);
        int o = r >> 4;
        int i = r & 15;
        ws[idx] = w[(o * CIN + i) * KK + k];
    }
    __syncthreads();

    const int is64 = g_is64;
    int lane = threadIdx.x & 31;
    int warp = threadIdx.x >> 5;
    int ohalf = warp >> 2;                         // 0 or 1
    int obase = ohalf * 16;                        // first output channel
    int h = blockIdx.x * HTILE + (warp & 3) * 32 + lane;
    bool active = h < H;

    unsigned long long acc2[16];
#pragma unroll
    for (int o = 0; o < 16; o++) acc2[o] = 0ULL;

    if (active) {
        int nidx[KK];
        if (is64) {
            const long long* nrow = (const long long*)neigh_raw + (long long)h * KK;
#pragma unroll
            for (int k = 0; k < KK; k++) {
                long long v = nrow[k];
                nidx[k] = (v < 0 || v >= (long long)H) ? H : (int)v;
            }
        } else {
            const int* nrow = (const int*)neigh_raw + (long long)h * KK;
#pragma unroll
            for (int k = 0; k < KK; k++) {
                int v = nrow[k];
                nidx[k] = ((unsigned)v >= (unsigned)H) ? H : v;
            }
        }

        // prefetch k=0 x row
        unsigned long long xq[8];
        {
            const ulonglong2* xp =
                reinterpret_cast<const ulonglong2*>(&g_xt[(size_t)nidx[0] * CIN]);
            ulonglong2 a = xp[0], b = xp[1], c = xp[2], d = xp[3];
            xq[0] = a.x; xq[1] = a.y; xq[2] = b.x; xq[3] = b.y;
            xq[4] = c.x; xq[5] = c.y; xq[6] = d.x; xq[7] = d.y;
        }

#pragma unroll 1
        for (int k = 0; k < KK; k++) {
            // prefetch next k's x row (off the critical path)
            unsigned long long xn[8];
            if (k + 1 < KK) {
                const ulonglong2* xp =
                    reinterpret_cast<const ulonglong2*>(&g_xt[(size_t)nidx[k + 1] * CIN]);
                ulonglong2 a = xp[0], b = xp[1], c = xp[2], d = xp[3];
                xn[0] = a.x; xn[1] = a.y; xn[2] = b.x; xn[3] = b.y;
                xn[4] = c.x; xn[5] = c.y; xn[6] = d.x; xn[7] = d.y;
            }

            const ulonglong2* wk =
                reinterpret_cast<const ulonglong2*>(&ws[k * COUT * CIN + obase * CIN]);
#pragma unroll
            for (int o = 0; o < 16; o++) {
                ulonglong2 w0 = wk[o * 4 + 0];
                ulonglong2 w1 = wk[o * 4 + 1];
                ulonglong2 w2 = wk[o * 4 + 2];
                ulonglong2 w3 = wk[o * 4 + 3];
                fma2(acc2[o], xq[0], w0.x);
                fma2(acc2[o], xq[1], w0.y);
                fma2(acc2[o], xq[2], w1.x);
                fma2(acc2[o], xq[3], w1.y);
                fma2(acc2[o], xq[4], w2.x);
                fma2(acc2[o], xq[5], w2.y);
                fma2(acc2[o], xq[6], w3.x);
                fma2(acc2[o], xq[7], w3.y);
            }
#pragma unroll
            for (int j = 0; j < 8; j++) xq[j] = xn[j];
        }
    }

    float acc[16];
#pragma unroll
    for (int o = 0; o < 16; o++) {
        float2 p = *reinterpret_cast<float2*>(&acc2[o]);
        acc[o] = p.x + p.y;
    }

    if (active) {
#pragma unroll
        for (int o = 0; o < 16; o++)
            out[(size_t)(obase + o) * H + h] = acc[o];
    }

    // --- deterministic block reduction of sum / sumsq ---
#pragma unroll
    for (int o = 0; o < 16; o++) {
        float v  = active ? acc[o] : 0.0f;
        float v2 = v * v;
#pragma unroll
        for (int off = 16; off > 0; off >>= 1) {
            v  += __shfl_xor_sync(0xFFFFFFFFu, v,  off);
            v2 += __shfl_xor_sync(0xFFFFFFFFu, v2, off);
        }
        if (lane == 0) { s_sum[warp][o] = v; s_sq[warp][o] = v2; }
    }
    __syncthreads();
    // thread t in [0,32): t<16 -> o=t from warps 0-3; t>=16 -> o=t from warps 4-7
    if (threadIdx.x < COUT) {
        int t = threadIdx.x;
        int wbase = (t < 16) ? 0 : 4;
        int oc = t & 15;
        float S = 0.0f, Q = 0.0f;
#pragma unroll
        for (int wdx = 0; wdx < 4; wdx++) {
            S += s_sum[wbase + wdx][oc];
            Q += s_sq [wbase + wdx][oc];
        }
        g_psum[(size_t)blockIdx.x * COUT + t] = S;
        g_psq [(size_t)blockIdx.x * COUT + t] = Q;
    }
}

// ---------------------------------------------------------------------------
__global__ void stats_kernel(const float* __restrict__ gamma,
                             const float* __restrict__ beta,
                             int H, int NB) {
    int o = blockIdx.x;
    float S = 0.0f, Q = 0.0f;
    for (int b = threadIdx.x; b < NB; b += blockDim.x) {
        S += g_psum[(size_t)b * COUT + o];
        Q += g_psq [(size_t)b * COUT + o];
    }
    __shared__ float ss[256], sq[256];
    ss[threadIdx.x] = S;
    sq[threadIdx.x] = Q;
    __syncthreads();
    for (int off = 128; off > 0; off >>= 1) {
        if (threadIdx.x < off) {
            ss[threadIdx.x] += ss[threadIdx.x + off];
            sq[threadIdx.x] += sq[threadIdx.x + off];
        }
        __syncthreads();
    }
    if (threadIdx.x == 0) {
        float invH = 1.0f / (float)H;
        float mean = ss[0] * invH;
        float var  = sq[0] * invH - mean * mean;
        float sc   = gamma[o] * rsqrtf(var + 1e-5f);
        g_scale[o] = sc;
        g_shift[o] = beta[o] - mean * sc;
    }
}

// ---------------------------------------------------------------------------
__global__ void norm_kernel(float* __restrict__ out, int H) {
    int o = blockIdx.y;
    int i = blockIdx.x * blockDim.x + threadIdx.x;
    int H4 = H >> 2;
    float sc = g_scale[o], sh = g_shift[o];
    float4* p = reinterpret_cast<float4*>(out + (size_t)o * H);
    if (i < H4) {
        float4 v = p[i];
        v.x = v.x * sc + sh;
        v.y = v.y * sc + sh;
        v.z = v.z * sc + sh;
        v.w = v.w * sc + sh;
        p[i] = v;
    }
    if (blockIdx.x == 0 && threadIdx.x < (H & 3)) {
        int hh = H4 * 4 + threadIdx.x;
        out[(size_t)o * H + hh] = out[(size_t)o * H + hh] * sc + sh;
    }
}

// ---------------------------------------------------------------------------
extern "C" void kernel_launch(void* const* d_in, const int* in_sizes, int n_in,
                              void* d_out, int out_size) {
    const float* x     = (const float*)d_in[0];
    const float* w     = (const float*)d_in[1];
    const float* gamma = (const float*)d_in[2];
    const float* beta  = (const float*)d_in[3];
    const void*  neigh = d_in[4];

    int H  = in_sizes[0] / CIN;
    int NB = (H + HTILE - 1) / HTILE;
    long long n_neigh = (long long)in_sizes[4];

    static const int kWsmemBytes = KK * COUT * CIN * (int)sizeof(float);  // 55296
    cudaFuncSetAttribute(conv_kernel,
                         cudaFuncAttributeMaxDynamicSharedMemorySize, kWsmemBytes);

    detect_kernel<<<1, 256>>>((const long long*)neigh, H, n_neigh);
    transpose_kernel<<<(H + 32 + 255) / 256, 256>>>(x, H);
    conv_kernel<<<NB, TPB, kWsmemBytes>>>(w, neigh, (float*)d_out, H);
    stats_kernel<<<COUT, 256>>>(gamma, beta, H, NB);
    dim3 ngrid((H / 4 + 255) / 256, COUT);
    norm_kernel<<<ngrid, 256>>>((float*)d_out, H);
}

// round 5
// speedup vs baseline: 1.0875x; 1.0875x over previous
#include <cuda_runtime.h>
#include <cuda_bf16.h>
#include <stdint.h>

#define CIN   16
#define COUT  32
#define KK    27
#define TPB   256
#define MAX_H 300064
#define MAX_B 4096

__device__ float g_xt[(size_t)MAX_H * CIN];   // transposed x: [h][c]; row H = zeros
__device__ int   g_nk[(size_t)KK * MAX_H];    // clamped indices, [k][h] layout
__device__ float g_psum[MAX_B * COUT];
__device__ float g_psq [MAX_B * COUT];
__device__ float g_scale[COUT];
__device__ float g_shift[COUT];
__device__ int   g_is64;

// packed fp32x2 FMA: d.lo += a.lo*b.lo ; d.hi += a.hi*b.hi
__device__ __forceinline__ void fma2(unsigned long long& d,
                                     unsigned long long a,
                                     unsigned long long b) {
    asm("fma.rn.f32x2 %0, %1, %2, %0;" : "+l"(d) : "l"(a), "l"(b));
}

// ---------------------------------------------------------------------------
__global__ void detect_kernel(const long long* __restrict__ neigh,
                              int H, long long n_elems) {
    __shared__ int bad;
    if (threadIdx.x == 0) bad = 0;
    __syncthreads();
    long long n64 = n_elems / 2;
    long long lim = n64 < 4096 ? n64 : 4096;
    for (long long i = threadIdx.x; i < lim; i += blockDim.x) {
        long long v = neigh[i];
        if (v < -1 || v >= (long long)H) bad = 1;
    }
    __syncthreads();
    if (threadIdx.x == 0) g_is64 = (bad == 0);
}

// ---------------------------------------------------------------------------
// Prep: clamp + transpose neigh -> g_nk[k][h] (int32). Invalid -> H (zero row).
// ---------------------------------------------------------------------------
__global__ void prep_kernel(const void* __restrict__ neigh_raw, int H) {
    int h = blockIdx.x * blockDim.x + threadIdx.x;
    if (h >= H) return;
    if (g_is64) {
        const long long* nrow = (const long long*)neigh_raw + (long long)h * KK;
#pragma unroll
        for (int k = 0; k < KK; k++) {
            long long v = nrow[k];
            g_nk[(size_t)k * MAX_H + h] = (v < 0 || v >= (long long)H) ? H : (int)v;
        }
    } else {
        const int* nrow = (const int*)neigh_raw + (long long)h * KK;
#pragma unroll
        for (int k = 0; k < KK; k++) {
            int v = nrow[k];
            g_nk[(size_t)k * MAX_H + h] = ((unsigned)v >= (unsigned)H) ? H : v;
        }
    }
}

// ---------------------------------------------------------------------------
__global__ void transpose_kernel(const float* __restrict__ x, int H) {
    int h = blockIdx.x * blockDim.x + threadIdx.x;
    float4* dst = reinterpret_cast<float4*>(&g_xt[(size_t)h * CIN]);
    if (h < H) {
        float v[CIN];
#pragma unroll
        for (int c = 0; c < CIN; c++) v[c] = x[(size_t)c * H + h];
#pragma unroll
        for (int j = 0; j < CIN / 4; j++)
            dst[j] = make_float4(v[4 * j], v[4 * j + 1], v[4 * j + 2], v[4 * j + 3]);
    } else if (h < H + 32 && h < MAX_H) {
        float4 z = make_float4(0.f, 0.f, 0.f, 0.f);
#pragma unroll
        for (int j = 0; j < CIN / 4; j++) dst[j] = z;
    }
}

// ---------------------------------------------------------------------------
// Gather-conv. One thread owns one h and all 32 outputs.
// Weights in smem as [k][i][o] (o contiguous) -> fma2 pairs over o:
//   acc2[m] = { y[2m], y[2m+1] }  (16 u64 accumulators = 32 regs)
// Indices streamed from g_nk (coalesced, 1 per k). Low regs -> 3 blocks/SM.
// ---------------------------------------------------------------------------
__global__ __launch_bounds__(TPB, 3)
void conv_kernel(const float* __restrict__ w,
                 float* __restrict__ out, int H) {
    extern __shared__ float ws[];                 // [k][i][o], 55.3 KB
    __shared__ float s_sum[TPB / 32][COUT];
    __shared__ float s_sq [TPB / 32][COUT];

    // ws[(k*CIN+i)*COUT + o] = w[(o*CIN+i)*KK + k]
    for (int idx = threadIdx.x; idx < KK * COUT * CIN; idx += TPB) {
        int k = idx / (CIN * COUT);
        int r = idx - k * (CIN * COUT);
        int i = r >> 5;
        int o = r & 31;
        ws[idx] = w[(o * CIN + i) * KK + k];
    }
    __syncthreads();

    int lane = threadIdx.x & 31;
    int warp = threadIdx.x >> 5;
    int h = blockIdx.x * TPB + threadIdx.x;
    bool active = h < H;
    int hc = active ? h : 0;   // inactive threads do harmless work on h=0

    unsigned long long acc2[16];
#pragma unroll
    for (int m = 0; m < 16; m++) acc2[m] = 0ULL;

#pragma unroll 1
    for (int k = 0; k < KK; k++) {
        int n = g_nk[(size_t)k * MAX_H + hc];          // coalesced LDG.32
        const float4* xp = reinterpret_cast<const float4*>(&g_xt[(size_t)n * CIN]);
        float4 x0 = xp[0], x1 = xp[1], x2 = xp[2], x3 = xp[3];
        float xv[CIN] = {x0.x, x0.y, x0.z, x0.w, x1.x, x1.y, x1.z, x1.w,
                         x2.x, x2.y, x2.z, x2.w, x3.x, x3.y, x3.z, x3.w};
#pragma unroll
        for (int i = 0; i < CIN; i++) {
            float2 t = make_float2(xv[i], xv[i]);
            unsigned long long xx = *reinterpret_cast<unsigned long long*>(&t);
            const ulonglong2* wrow =
                reinterpret_cast<const ulonglong2*>(&ws[(k * CIN + i) * COUT]);
#pragma unroll
            for (int j = 0; j < 8; j++) {
                ulonglong2 wv = wrow[j];               // LDS.128 broadcast: o=4j..4j+3
                fma2(acc2[2 * j],     xx, wv.x);
                fma2(acc2[2 * j + 1], xx, wv.y);
            }
        }
    }

    float acc[COUT];
#pragma unroll
    for (int m = 0; m < 16; m++) {
        float2 p = *reinterpret_cast<float2*>(&acc2[m]);
        acc[2 * m]     = p.x;
        acc[2 * m + 1] = p.y;
    }

    if (active) {
#pragma unroll
        for (int o = 0; o < COUT; o++) out[(size_t)o * H + h] = acc[o];
    }

    // --- deterministic block reduction of sum / sumsq per channel ---
#pragma unroll
    for (int o = 0; o < COUT; o++) {
        float v  = active ? acc[o] : 0.0f;
        float v2 = v * v;
#pragma unroll
        for (int off = 16; off > 0; off >>= 1) {
            v  += __shfl_xor_sync(0xFFFFFFFFu, v,  off);
            v2 += __shfl_xor_sync(0xFFFFFFFFu, v2, off);
        }
        if (lane == 0) { s_sum[warp][o] = v; s_sq[warp][o] = v2; }
    }
    __syncthreads();
    if (threadIdx.x < COUT) {
        float S = 0.0f, Q = 0.0f;
#pragma unroll
        for (int wdx = 0; wdx < TPB / 32; wdx++) {
            S += s_sum[wdx][threadIdx.x];
            Q += s_sq [wdx][threadIdx.x];
        }
        g_psum[(size_t)blockIdx.x * COUT + threadIdx.x] = S;
        g_psq [(size_t)blockIdx.x * COUT + threadIdx.x] = Q;
    }
}

// ---------------------------------------------------------------------------
__global__ void stats_kernel(const float* __restrict__ gamma,
                             const float* __restrict__ beta,
                             int H, int NB) {
    int o = blockIdx.x;
    float S = 0.0f, Q = 0.0f;
    for (int b = threadIdx.x; b < NB; b += blockDim.x) {
        S += g_psum[(size_t)b * COUT + o];
        Q += g_psq [(size_t)b * COUT + o];
    }
    __shared__ float ss[256], sq[256];
    ss[threadIdx.x] = S;
    sq[threadIdx.x] = Q;
    __syncthreads();
    for (int off = 128; off > 0; off >>= 1) {
        if (threadIdx.x < off) {
            ss[threadIdx.x] += ss[threadIdx.x + off];
            sq[threadIdx.x] += sq[threadIdx.x + off];
        }
        __syncthreads();
    }
    if (threadIdx.x == 0) {
        float invH = 1.0f / (float)H;
        float mean = ss[0] * invH;
        float var  = sq[0] * invH - mean * mean;
        float sc   = gamma[o] * rsqrtf(var + 1e-5f);
        g_scale[o] = sc;
        g_shift[o] = beta[o] - mean * sc;
    }
}

// ---------------------------------------------------------------------------
__global__ void norm_kernel(float* __restrict__ out, int H) {
    int o = blockIdx.y;
    int i = blockIdx.x * blockDim.x + threadIdx.x;
    int H4 = H >> 2;
    float sc = g_scale[o], sh = g_shift[o];
    float4* p = reinterpret_cast<float4*>(out + (size_t)o * H);
    if (i < H4) {
        float4 v = p[i];
        v.x = v.x * sc + sh;
        v.y = v.y * sc + sh;
        v.z = v.z * sc + sh;
        v.w = v.w * sc + sh;
        p[i] = v;
    }
    if (blockIdx.x == 0 && threadIdx.x < (H & 3)) {
        int hh = H4 * 4 + threadIdx.x;
        out[(size_t)o * H + hh] = out[(size_t)o * H + hh] * sc + sh;
    }
}

// ---------------------------------------------------------------------------
extern "C" void kernel_launch(void* const* d_in, const int* in_sizes, int n_in,
                              void* d_out, int out_size) {
    const float* x     = (const float*)d_in[0];
    const float* w     = (const float*)d_in[1];
    const float* gamma = (const float*)d_in[2];
    const float* beta  = (const float*)d_in[3];
    const void*  neigh = d_in[4];

    int H  = in_sizes[0] / CIN;
    int NB = (H + TPB - 1) / TPB;
    long long n_neigh = (long long)in_sizes[4];

    static const int kWsmemBytes = KK * COUT * CIN * (int)sizeof(float);  // 55296
    cudaFuncSetAttribute(conv_kernel,
                         cudaFuncAttributeMaxDynamicSharedMemorySize, kWsmemBytes);

    detect_kernel<<<1, 256>>>((const long long*)neigh, H, n_neigh);
    prep_kernel<<<(H + 255) / 256, 256>>>(neigh, H);
    transpose_kernel<<<(H + 32 + 255) / 256, 256>>>(x, H);
    conv_kernel<<<NB, TPB, kWsmemBytes>>>(w, (float*)d_out, H);
    stats_kernel<<<COUT, 256>>>(gamma, beta, H, NB);
    dim3 ngrid((H / 4 + 255) / 256, COUT);
    norm_kernel<<<ngrid, 256>>>((float*)d_out, H);
}

// round 6
// speedup vs baseline: 1.7897x; 1.6457x over previous
#include <cuda_runtime.h>
#include <cuda_bf16.h>
#include <stdint.h>

#define CIN   16
#define COUT  32
#define KK    27
#define TPB   256
#define HBLK  512                         // h per block (2 per thread)
#define MAX_H 300576                      // >= ceil(H/512)*512, + pad row
#define MAX_B 1024

__device__ float g_xt[(size_t)MAX_H * CIN];   // transposed x: [h][c]; row H = zeros
__device__ int   g_nk[(size_t)KK * MAX_H];    // clamped indices, [k][h] layout
__device__ float g_psum[MAX_B * COUT];
__device__ float g_psq [MAX_B * COUT];
__device__ float g_scale[COUT];
__device__ float g_shift[COUT];
__device__ int   g_is64;

typedef unsigned long long ull;

// packed fp32x2 FMA: d.lo += a.lo*b.lo ; d.hi += a.hi*b.hi
__device__ __forceinline__ void fma2(ull& d, ull a, ull b) {
    asm("fma.rn.f32x2 %0, %1, %2, %0;" : "+l"(d) : "l"(a), "l"(b));
}
__device__ __forceinline__ ull pack2(float v) {
    float2 t = make_float2(v, v);
    return *reinterpret_cast<ull*>(&t);
}

// ---------------------------------------------------------------------------
__global__ void detect_kernel(const long long* __restrict__ neigh,
                              int H, long long n_elems) {
    __shared__ int bad;
    if (threadIdx.x == 0) bad = 0;
    __syncthreads();
    long long n64 = n_elems / 2;
    long long lim = n64 < 4096 ? n64 : 4096;
    for (long long i = threadIdx.x; i < lim; i += blockDim.x) {
        long long v = neigh[i];
        if (v < -1 || v >= (long long)H) bad = 1;
    }
    __syncthreads();
    if (threadIdx.x == 0) g_is64 = (bad == 0);
}

// ---------------------------------------------------------------------------
// Prep: clamp + transpose neigh -> g_nk[k][h]; h in [H, Hcover) -> H (zero row)
// ---------------------------------------------------------------------------
__global__ void prep_kernel(const void* __restrict__ neigh_raw, int H, int Hcover) {
    int h = blockIdx.x * blockDim.x + threadIdx.x;
    if (h >= Hcover) return;
    if (h >= H) {
#pragma unroll
        for (int k = 0; k < KK; k++) g_nk[(size_t)k * MAX_H + h] = H;
        return;
    }
    if (g_is64) {
        const long long* nrow = (const long long*)neigh_raw + (long long)h * KK;
#pragma unroll
        for (int k = 0; k < KK; k++) {
            long long v = nrow[k];
            g_nk[(size_t)k * MAX_H + h] = (v < 0 || v >= (long long)H) ? H : (int)v;
        }
    } else {
        const int* nrow = (const int*)neigh_raw + (long long)h * KK;
#pragma unroll
        for (int k = 0; k < KK; k++) {
            int v = nrow[k];
            g_nk[(size_t)k * MAX_H + h] = ((unsigned)v >= (unsigned)H) ? H : v;
        }
    }
}

// ---------------------------------------------------------------------------
__global__ void transpose_kernel(const float* __restrict__ x, int H) {
    int h = blockIdx.x * blockDim.x + threadIdx.x;
    float4* dst = reinterpret_cast<float4*>(&g_xt[(size_t)h * CIN]);
    if (h < H) {
        float v[CIN];
#pragma unroll
        for (int c = 0; c < CIN; c++) v[c] = x[(size_t)c * H + h];
#pragma unroll
        for (int j = 0; j < CIN / 4; j++)
            dst[j] = make_float4(v[4 * j], v[4 * j + 1], v[4 * j + 2], v[4 * j + 3]);
    } else if (h < H + 32 && h < MAX_H) {
        float4 z = make_float4(0.f, 0.f, 0.f, 0.f);
#pragma unroll
        for (int j = 0; j < CIN / 4; j++) dst[j] = z;
    }
}

// ---------------------------------------------------------------------------
// Gather-conv, cooperative-gather + 2h/thread version.
//
// Per warp, per k:
//   stage: 8 LDG.128 (lane groups of 4 fetch one 64B row each -> 8 rows/instr,
//          8 wavefronts instead of 32), STS to warp-private smem tile
//          laid out [quad][row] (plane stride 264 words -> bank-clean LDS.128)
//   compute: thread t consumes rows t and t+32; weights [k][i][o] in smem,
//          each broadcast LDS.128 feeds 4 fma2 (2 o-pairs x 2 h).
// Accs: acc_a/acc_b[m] = {y[2m],y[2m+1]} for h0/h1 -> 32 u64 = 64 regs.
// ---------------------------------------------------------------------------
#define XT_PLANE 264                       // words per quad-plane (64*4 + 8 pad)
#define XT_WARP  (4 * XT_PLANE)            // 1056 words per warp

__global__ __launch_bounds__(TPB, 2)
void conv_kernel(const float* __restrict__ w,
                 float* __restrict__ out, int H) {
    extern __shared__ float smem[];
    float* ws = smem;                                  // [k][i][o], 13824 floats
    __shared__ float s_sum[TPB / 32][COUT];
    __shared__ float s_sq [TPB / 32][COUT];

    // ws[(k*CIN+i)*COUT + o] = w[(o*CIN+i)*KK + k]
    for (int idx = threadIdx.x; idx < KK * COUT * CIN; idx += TPB) {
        int k = idx / (CIN * COUT);
        int r = idx - k * (CIN * COUT);
        int i = r >> 5;
        int o = r & 31;
        ws[idx] = w[(o * CIN + i) * KK + k];
    }
    __syncthreads();

    int lane = threadIdx.x & 31;
    int warp = threadIdx.x >> 5;
    float* xw = smem + KK * CIN * COUT + warp * XT_WARP;

    int warpbase = blockIdx.x * HBLK + warp * 64;
    int h0 = warpbase + lane;
    int h1 = h0 + 32;

    int jq   = lane & 3;                    // quad this lane fetches
    int rsub = lane >> 2;                   // row-within-8 this lane fetches

    ull acc_a[16], acc_b[16];
#pragma unroll
    for (int m = 0; m < 16; m++) { acc_a[m] = 0ULL; acc_b[m] = 0ULL; }

#pragma unroll 1
    for (int k = 0; k < KK; k++) {
        // ---- stage 64 gathered rows into smem tile ----
#pragma unroll
        for (int g = 0; g < 8; g++) {
            int r = g * 8 + rsub;
            int n = g_nk[(size_t)k * MAX_H + warpbase + r];
            float4 v = reinterpret_cast<const float4*>(&g_xt[(size_t)n * CIN])[jq];
            *reinterpret_cast<float4*>(&xw[jq * XT_PLANE + r * 4]) = v;
        }
        __syncwarp();

        // ---- compute ----
#pragma unroll
        for (int q = 0; q < 4; q++) {
            float4 va = *reinterpret_cast<const float4*>(&xw[q * XT_PLANE + lane * 4]);
            float4 vb = *reinterpret_cast<const float4*>(&xw[q * XT_PLANE + (lane + 32) * 4]);
            float fa[4] = {va.x, va.y, va.z, va.w};
            float fb[4] = {vb.x, vb.y, vb.z, vb.w};
#pragma unroll
            for (int e = 0; e < 4; e++) {
                int i = q * 4 + e;
                ull xa = pack2(fa[e]);
                ull xb = pack2(fb[e]);
                const ulonglong2* wr =
                    reinterpret_cast<const ulonglong2*>(&ws[(k * CIN + i) * COUT]);
#pragma unroll
                for (int m4 = 0; m4 < 8; m4++) {
                    ulonglong2 wv = wr[m4];            // broadcast LDS.128
                    fma2(acc_a[2 * m4],     xa, wv.x);
                    fma2(acc_a[2 * m4 + 1], xa, wv.y);
                    fma2(acc_b[2 * m4],     xb, wv.x);
                    fma2(acc_b[2 * m4 + 1], xb, wv.y);
                }
            }
        }
        __syncwarp();                                  // protect tile before next stage
    }

    float ya[COUT], yb[COUT];
#pragma unroll
    for (int m = 0; m < 16; m++) {
        float2 pa = *reinterpret_cast<float2*>(&acc_a[m]);
        float2 pb = *reinterpret_cast<float2*>(&acc_b[m]);
        ya[2 * m] = pa.x; ya[2 * m + 1] = pa.y;
        yb[2 * m] = pb.x; yb[2 * m + 1] = pb.y;
    }

    bool act0 = h0 < H, act1 = h1 < H;
    if (act0) {
#pragma unroll
        for (int o = 0; o < COUT; o++) out[(size_t)o * H + h0] = ya[o];
    }
    if (act1) {
#pragma unroll
        for (int o = 0; o < COUT; o++) out[(size_t)o * H + h1] = yb[o];
    }

    // --- deterministic block reduction (inactive h contribute exact 0) ---
#pragma unroll
    for (int o = 0; o < COUT; o++) {
        float v  = ya[o] + yb[o];
        float v2 = ya[o] * ya[o] + yb[o] * yb[o];
#pragma unroll
        for (int off = 16; off > 0; off >>= 1) {
            v  += __shfl_xor_sync(0xFFFFFFFFu, v,  off);
            v2 += __shfl_xor_sync(0xFFFFFFFFu, v2, off);
        }
        if (lane == 0) { s_sum[warp][o] = v; s_sq[warp][o] = v2; }
    }
    __syncthreads();
    if (threadIdx.x < COUT) {
        float S = 0.0f, Q = 0.0f;
#pragma unroll
        for (int wdx = 0; wdx < TPB / 32; wdx++) {
            S += s_sum[wdx][threadIdx.x];
            Q += s_sq [wdx][threadIdx.x];
        }
        g_psum[(size_t)blockIdx.x * COUT + threadIdx.x] = S;
        g_psq [(size_t)blockIdx.x * COUT + threadIdx.x] = Q;
    }
}

// ---------------------------------------------------------------------------
__global__ void stats_kernel(const float* __restrict__ gamma,
                             const float* __restrict__ beta,
                             int H, int NB) {
    int o = blockIdx.x;
    float S = 0.0f, Q = 0.0f;
    for (int b = threadIdx.x; b < NB; b += blockDim.x) {
        S += g_psum[(size_t)b * COUT + o];
        Q += g_psq [(size_t)b * COUT + o];
    }
    __shared__ float ss[256], sq[256];
    ss[threadIdx.x] = S;
    sq[threadIdx.x] = Q;
    __syncthreads();
    for (int off = 128; off > 0; off >>= 1) {
        if (threadIdx.x < off) {
            ss[threadIdx.x] += ss[threadIdx.x + off];
            sq[threadIdx.x] += sq[threadIdx.x + off];
        }
        __syncthreads();
    }
    if (threadIdx.x == 0) {
        float invH = 1.0f / (float)H;
        float mean = ss[0] * invH;
        float var  = sq[0] * invH - mean * mean;
        float sc   = gamma[o] * rsqrtf(var + 1e-5f);
        g_scale[o] = sc;
        g_shift[o] = beta[o] - mean * sc;
    }
}

// ---------------------------------------------------------------------------
__global__ void norm_kernel(float* __restrict__ out, int H) {
    int o = blockIdx.y;
    int i = blockIdx.x * blockDim.x + threadIdx.x;
    int H4 = H >> 2;
    float sc = g_scale[o], sh = g_shift[o];
    float4* p = reinterpret_cast<float4*>(out + (size_t)o * H);
    if (i < H4) {
        float4 v = p[i];
        v.x = v.x * sc + sh;
        v.y = v.y * sc + sh;
        v.z = v.z * sc + sh;
        v.w = v.w * sc + sh;
        p[i] = v;
    }
    if (blockIdx.x == 0 && threadIdx.x < (H & 3)) {
        int hh = H4 * 4 + threadIdx.x;
        out[(size_t)o * H + hh] = out[(size_t)o * H + hh] * sc + sh;
    }
}

// ---------------------------------------------------------------------------
extern "C" void kernel_launch(void* const* d_in, const int* in_sizes, int n_in,
                              void* d_out, int out_size) {
    const float* x     = (const float*)d_in[0];
    const float* w     = (const float*)d_in[1];
    const float* gamma = (const float*)d_in[2];
    const float* beta  = (const float*)d_in[3];
    const void*  neigh = d_in[4];

    int H  = in_sizes[0] / CIN;
    int NB = (H + HBLK - 1) / HBLK;
    int Hcover = NB * HBLK;
    long long n_neigh = (long long)in_sizes[4];

    static const int kSmemBytes =
        (KK * COUT * CIN + 8 * XT_WARP) * (int)sizeof(float);   // 89088
    cudaFuncSetAttribute(conv_kernel,
                         cudaFuncAttributeMaxDynamicSharedMemorySize, kSmemBytes);

    detect_kernel<<<1, 256>>>((const long long*)neigh, H, n_neigh);
    prep_kernel<<<(Hcover + 255) / 256, 256>>>(neigh, H, Hcover);
    transpose_kernel<<<(H + 32 + 255) / 256, 256>>>(x, H);
    conv_kernel<<<NB, TPB, kSmemBytes>>>(w, (float*)d_out, H);
    stats_kernel<<<COUT, 256>>>(gamma, beta, H, NB);
    dim3 ngrid((H / 4 + 255) / 256, COUT);
    norm_kernel<<<ngrid, 256>>>((float*)d_out, H);
}